// round 17
// baseline (speedup 1.0000x reference)
#include <cuda_runtime.h>
#include <cuda_fp16.h>
#include <cstdint>

#define NPTS 8192
#define KNN  8

// ---------------- scratch (device globals: no allocations allowed) ----------
__device__ int   g_knn[NPTS * KNN];
__device__ unsigned short g_x1h[NPTS * 128];  // edgeconv1 output fp16 [i][k]
__device__ unsigned short g_Ah[NPTS * 128];   // fp16: x1 @ (W3a-W3b) + b3
__device__ unsigned short g_Bh[NPTS * 128];   // fp16: x1 @ W3b
__device__ unsigned short g_w2h[128 * 64];    // W2^T fp16 [c][u]
__device__ unsigned short g_w3h[256 * 128];   // [Wd^T ; Wb^T] fp16 [n][k]
__device__ unsigned short g_w4h[256 * 128];   // W4^T fp16 [c][k]

// ---------------- helpers ----------------------------------------------------
__device__ __forceinline__ uint32_t smem_u32(const void* p) {
    uint32_t a;
    asm("{ .reg .u64 t; cvta.to.shared.u64 t, %1; cvt.u32.u64 %0, t; }"
        : "=r"(a) : "l"(p));
    return a;
}

// ---------------- Kernels 0a-0c: weight fp16 conversions (launch slots 1-3) -
__global__ __launch_bounds__(256) void w2conv_kernel(const float* __restrict__ W2) {
    int idx = blockIdx.x * 256 + threadIdx.x;      // 8192
    int c = idx >> 6, u = idx & 63;
    g_w2h[idx] = __half_as_ushort(__float2half_rn(W2[u*128 + c]));
}
__global__ __launch_bounds__(256) void w3conv_kernel(const float* __restrict__ W3) {
    int idx = blockIdx.x * 256 + threadIdx.x;      // 16384
    int k = idx >> 7, c = idx & 127;
    float wa = W3[k*128 + c];
    float wb = W3[(k+128)*128 + c];
    g_w3h[c*128 + k]       = __half_as_ushort(__float2half_rn(wa - wb));
    g_w3h[(128+c)*128 + k] = __half_as_ushort(__float2half_rn(wb));
}
__global__ __launch_bounds__(256) void w4conv_kernel(const float* __restrict__ W4) {
    int idx = blockIdx.x * 256 + threadIdx.x;      // 32768
    int k = idx >> 8, c = idx & 255;
    g_w4h[c*128 + k] = __half_as_ushort(__float2half_rn(W4[k*256 + c]));
}

// ---------------- Kernel 1: KNN, 2 queries/warp, distributed top-8 ----------
// List A in lanes 0..7, list B in lanes 8..15 (sorted u64 keys each).
// Candidate tile reads amortized over both queries.
__global__ __launch_bounds__(256) void knn_kernel(const float* __restrict__ pts) {
    const int TS = 2048;
    __shared__ float4 sp[TS];
    const int lane = threadIdx.x & 31;
    const int warp = threadIdx.x >> 5;
    const int qiA = blockIdx.x * 16 + warp * 2;
    const int qiB = qiA + 1;
    const unsigned FULL = 0xFFFFFFFFu;

    const float axA = -2.0f*pts[qiA*3+0], ayA = -2.0f*pts[qiA*3+1],
                azA = -2.0f*pts[qiA*3+2];
    const float axB = -2.0f*pts[qiB*3+0], ayB = -2.0f*pts[qiB*3+1],
                azB = -2.0f*pts[qiB*3+2];

    const float INF = 3.4028235e38f;
    unsigned long long mykey = 0xFFFFFFFFFFFFFFFFULL;
    float myd = INF;
    float TfA = INF, TfB = INF;

    for (int base = 0; base < NPTS; base += TS) {
        __syncthreads();
        for (int t = threadIdx.x; t < TS; t += 256) {
            float x = pts[(base+t)*3+0];
            float y = pts[(base+t)*3+1];
            float z = pts[(base+t)*3+2];
            sp[t] = make_float4(x, y, z, x*x + y*y + z*z);
        }
        __syncthreads();

        for (int jb = 0; jb < TS; jb += 256) {
            float dA[8], dB[8];
            #pragma unroll
            for (int q = 0; q < 8; q++) {
                float4 p = sp[jb + q*32 + lane];
                dA[q] = fmaf(axA, p.x, fmaf(ayA, p.y, fmaf(azA, p.z, p.w)));
                dB[q] = fmaf(axB, p.x, fmaf(ayB, p.y, fmaf(azB, p.z, p.w)));
            }
            float mA = fminf(fminf(fminf(dA[0],dA[1]), fminf(dA[2],dA[3])),
                             fminf(fminf(dA[4],dA[5]), fminf(dA[6],dA[7])));
            float mB = fminf(fminf(fminf(dB[0],dB[1]), fminf(dB[2],dB[3])),
                             fminf(fminf(dB[4],dB[5]), fminf(dB[6],dB[7])));

            if (__any_sync(FULL, mA < TfA)) {
                #pragma unroll
                for (int q = 0; q < 8; q++) {
                    unsigned bal = __ballot_sync(FULL, dA[q] < TfA);
                    while (bal) {
                        const int src = __ffs(bal) - 1;
                        const float kd = __shfl_sync(FULL, dA[q], src);
                        const unsigned kidx =
                            (unsigned)(base + jb + q*32 + src);
                        unsigned ob = __float_as_uint(kd);
                        ob ^= ((unsigned)((int)ob >> 31)) | 0x80000000u;
                        const unsigned long long k =
                            ((unsigned long long)ob << 32) | kidx;
                        unsigned long long p = __shfl_up_sync(FULL, mykey, 1);
                        float pd = __shfl_up_sync(FULL, myd, 1);
                        if (lane == 0) { p = 0ULL; pd = -INF; }
                        if (lane < 8) {
                            const bool keep = mykey < k;
                            const bool useP = p > k;
                            mykey = keep ? mykey : (useP ? p  : k);
                            myd   = keep ? myd   : (useP ? pd : kd);
                        }
                        TfA = __shfl_sync(FULL, myd, 7);
                        bal &= bal - 1;
                        bal &= __ballot_sync(FULL, dA[q] < TfA);
                    }
                }
            }
            if (__any_sync(FULL, mB < TfB)) {
                #pragma unroll
                for (int q = 0; q < 8; q++) {
                    unsigned bal = __ballot_sync(FULL, dB[q] < TfB);
                    while (bal) {
                        const int src = __ffs(bal) - 1;
                        const float kd = __shfl_sync(FULL, dB[q], src);
                        const unsigned kidx =
                            (unsigned)(base + jb + q*32 + src);
                        unsigned ob = __float_as_uint(kd);
                        ob ^= ((unsigned)((int)ob >> 31)) | 0x80000000u;
                        const unsigned long long k =
                            ((unsigned long long)ob << 32) | kidx;
                        unsigned long long p = __shfl_up_sync(FULL, mykey, 1);
                        float pd = __shfl_up_sync(FULL, myd, 1);
                        if (lane == 8) { p = 0ULL; pd = -INF; }
                        if (lane >= 8 && lane < 16) {
                            const bool keep = mykey < k;
                            const bool useP = p > k;
                            mykey = keep ? mykey : (useP ? p  : k);
                            myd   = keep ? myd   : (useP ? pd : kd);
                        }
                        TfB = __shfl_sync(FULL, myd, 15);
                        bal &= bal - 1;
                        bal &= __ballot_sync(FULL, dB[q] < TfB);
                    }
                }
            }
        }
    }

    if (lane < 8)
        g_knn[qiA*KNN + lane] = (int)(mykey & 0xFFFFFFFFu);
    else if (lane < 16)
        g_knn[qiB*KNN + (lane - 8)] = (int)(mykey & 0xFFFFFFFFu);
}

// ---------------- Kernel 2: EdgeConv1, layer2 on tensor cores ---------------
#define PADK2 72
__global__ __launch_bounds__(256) void conv1_kernel(
    const float* __restrict__ pts,
    const float* __restrict__ W1, const float* __restrict__ b1,
    const float* __restrict__ b2)
{
    __shared__ float  se[16][8][6];
    __shared__ __half sE[128 * PADK2];
    __shared__ __half sW[128 * PADK2];
    const int t    = threadIdx.x;
    const int lane = t & 31;
    const int w    = t >> 5;
    const int p0   = blockIdx.x * 16;

    {
        #pragma unroll
        for (int g = 0; g < 4; g++) {
            int idx = t + g*256;
            int row = idx >> 3, part = idx & 7;
            uint4 v = *((const uint4*)(g_w2h + row*64) + part);
            *((uint4*)(sW + row*PADK2) + part) = v;
        }
    }
    if (t < 128) {
        int p = t >> 3, e = t & 7;
        int i = p0 + p;
        int j = g_knn[i*KNN + e];
        float xi0 = pts[i*3+0], xi1 = pts[i*3+1], xi2 = pts[i*3+2];
        float xj0 = pts[j*3+0], xj1 = pts[j*3+1], xj2 = pts[j*3+2];
        se[p][e][0] = xi0; se[p][e][1] = xi1; se[p][e][2] = xi2;
        se[p][e][3] = xj0 - xi0; se[p][e][4] = xj1 - xi1; se[p][e][5] = xj2 - xi2;
    }

    const int u = t & 63;
    float w1r[6];
    #pragma unroll
    for (int f = 0; f < 6; f++) w1r[f] = W1[f*64 + u];
    const float b1r = b1[u];
    __syncthreads();

    #pragma unroll
    for (int r = 0; r < 32; r++) {
        int pe = (t >> 6) + r * 4;
        int p = pe >> 3, e = pe & 7;
        float acc = b1r;
        #pragma unroll
        for (int f = 0; f < 6; f++) acc += se[p][e][f] * w1r[f];
        sE[pe * PADK2 + u] = __float2half_rn(fmaxf(acc, 0.0f));
    }
    __syncthreads();

    const int mw = w & 1, nw = w >> 1;
    const int m0 = mw * 64;
    const int n0 = nw * 32;

    const uint32_t sE32 = smem_u32(sE), sW32 = smem_u32(sW);
    const uint32_t aoff = ((uint32_t)(m0 + (lane & 15)) * PADK2 +
                           ((lane >> 4) & 1) * 8) * 2;
    const uint32_t boff = ((uint32_t)(n0 + ((lane >> 4) & 1) * 8 + (lane & 7)) * PADK2 +
                           ((lane >> 3) & 1) * 8) * 2;

    float d[4][4][4];
    #pragma unroll
    for (int mt = 0; mt < 4; mt++)
        #pragma unroll
        for (int nt = 0; nt < 4; nt++)
            { d[mt][nt][0]=0.f; d[mt][nt][1]=0.f; d[mt][nt][2]=0.f; d[mt][nt][3]=0.f; }

    #pragma unroll
    for (int k16 = 0; k16 < 4; k16++) {
        const uint32_t kb = k16 * 32;
        uint32_t a[4][4];
        #pragma unroll
        for (int mt = 0; mt < 4; mt++) {
            asm volatile(
                "ldmatrix.sync.aligned.m8n8.x4.shared.b16 {%0,%1,%2,%3}, [%4];"
                : "=r"(a[mt][0]), "=r"(a[mt][1]), "=r"(a[mt][2]), "=r"(a[mt][3])
                : "r"(sE32 + aoff + (uint32_t)mt * (16 * PADK2 * 2) + kb));
        }
        uint32_t b[8];
        #pragma unroll
        for (int ntp = 0; ntp < 2; ntp++) {
            asm volatile(
                "ldmatrix.sync.aligned.m8n8.x4.shared.b16 {%0,%1,%2,%3}, [%4];"
                : "=r"(b[ntp*4]), "=r"(b[ntp*4+1]), "=r"(b[ntp*4+2]), "=r"(b[ntp*4+3])
                : "r"(sW32 + boff + (uint32_t)ntp * (16 * PADK2 * 2) + kb));
        }
        #pragma unroll
        for (int mt = 0; mt < 4; mt++) {
            #pragma unroll
            for (int nt = 0; nt < 4; nt++) {
                const int bi = (nt >> 1) * 4 + (nt & 1) * 2;
                asm volatile(
                    "mma.sync.aligned.m16n8k16.row.col.f32.f16.f16.f32 "
                    "{%0,%1,%2,%3}, {%4,%5,%6,%7}, {%8,%9}, {%0,%1,%2,%3};"
                    : "+f"(d[mt][nt][0]), "+f"(d[mt][nt][1]),
                      "+f"(d[mt][nt][2]), "+f"(d[mt][nt][3])
                    : "r"(a[mt][0]), "r"(a[mt][1]), "r"(a[mt][2]), "r"(a[mt][3]),
                      "r"(b[bi]), "r"(b[bi+1]));
            }
        }
    }

    #pragma unroll
    for (int mt = 0; mt < 4; mt++) {
        #pragma unroll
        for (int nt = 0; nt < 4; nt++) {
            float v0 = d[mt][nt][0], v1 = d[mt][nt][1];
            float v2 = d[mt][nt][2], v3 = d[mt][nt][3];
            #pragma unroll
            for (int off = 4; off <= 16; off <<= 1) {
                v0 = fmaxf(v0, __shfl_xor_sync(0xFFFFFFFFu, v0, off));
                v1 = fmaxf(v1, __shfl_xor_sync(0xFFFFFFFFu, v1, off));
                v2 = fmaxf(v2, __shfl_xor_sync(0xFFFFFFFFu, v2, off));
                v3 = fmaxf(v3, __shfl_xor_sync(0xFFFFFFFFu, v3, off));
            }
            if (lane < 4) {
                const int c = n0 + nt * 8 + lane * 2;
                const float2 bb = *(const float2*)(b2 + c);
                const int pA = p0 + mw * 8 + mt * 2;
                __half2 hA = __floats2half2_rn(fmaxf(v0 + bb.x, 0.0f),
                                               fmaxf(v1 + bb.y, 0.0f));
                __half2 hB = __floats2half2_rn(fmaxf(v2 + bb.x, 0.0f),
                                               fmaxf(v3 + bb.y, 0.0f));
                *(uint32_t*)(g_x1h + (size_t)(pA    ) * 128 + c) = *(uint32_t*)&hA;
                *(uint32_t*)(g_x1h + (size_t)(pA + 1) * 128 + c) = *(uint32_t*)&hB;
            }
        }
    }
}

// ---------------- Kernel 3: pre2 as fp16 GEMM, fp16 outputs -----------------
#define PADK 136
#define P_A_ELEMS (64  * PADK)
#define P_B_ELEMS (256 * PADK)
#define PRE2_SMEM ((P_A_ELEMS + P_B_ELEMS) * 2)

__global__ __launch_bounds__(256, 2) void pre2t_kernel(const float* __restrict__ b3)
{
    extern __shared__ __align__(16) char smem[];
    __half* sA = (__half*)smem;
    __half* sB = sA + P_A_ELEMS;

    const int t    = threadIdx.x;
    const int lane = t & 31;
    const int w    = t >> 5;
    const int i0   = blockIdx.x * 64;

    {
        const int r = t >> 2, q = t & 3;
        #pragma unroll
        for (int g = 0; g < 4; g++) {
            uint4 v = *((const uint4*)(g_x1h + (size_t)(i0 + r) * 128) + q*4 + g);
            *((uint4*)(sA + r * PADK) + q*4 + g) = v;
        }
    }
    {
        const uint4* s4 = (const uint4*)(g_w3h + (size_t)t * 128);
        uint4* d4 = (uint4*)(sB + t * PADK);
        #pragma unroll
        for (int kg = 0; kg < 16; kg++) d4[kg] = s4[kg];
    }
    __syncthreads();

    const int mw  = w & 1;
    const int nwp = w >> 1;
    const int m0  = mw * 32;
    const int n0  = nwp * 64;

    const uint32_t sA32 = smem_u32(sA), sB32 = smem_u32(sB);
    const uint32_t aoff = ((uint32_t)(m0 + (lane & 15)) * PADK +
                           ((lane >> 4) & 1) * 8) * 2;
    const uint32_t boff = ((uint32_t)(n0 + ((lane >> 4) & 1) * 8 + (lane & 7)) * PADK +
                           ((lane >> 3) & 1) * 8) * 2;

    float d[2][8][4];
    #pragma unroll
    for (int mt = 0; mt < 2; mt++)
        #pragma unroll
        for (int nt = 0; nt < 8; nt++)
            { d[mt][nt][0]=0.f; d[mt][nt][1]=0.f; d[mt][nt][2]=0.f; d[mt][nt][3]=0.f; }

    #pragma unroll
    for (int k16 = 0; k16 < 8; k16++) {
        const uint32_t kb = k16 * 32;
        uint32_t a[2][4];
        #pragma unroll
        for (int mt = 0; mt < 2; mt++) {
            asm volatile(
                "ldmatrix.sync.aligned.m8n8.x4.shared.b16 {%0,%1,%2,%3}, [%4];"
                : "=r"(a[mt][0]), "=r"(a[mt][1]), "=r"(a[mt][2]), "=r"(a[mt][3])
                : "r"(sA32 + aoff + (uint32_t)mt * (16 * PADK * 2) + kb));
        }
        uint32_t b[16];
        #pragma unroll
        for (int ntp = 0; ntp < 4; ntp++) {
            asm volatile(
                "ldmatrix.sync.aligned.m8n8.x4.shared.b16 {%0,%1,%2,%3}, [%4];"
                : "=r"(b[ntp*4]), "=r"(b[ntp*4+1]), "=r"(b[ntp*4+2]), "=r"(b[ntp*4+3])
                : "r"(sB32 + boff + (uint32_t)ntp * (16 * PADK * 2) + kb));
        }
        #pragma unroll
        for (int mt = 0; mt < 2; mt++) {
            #pragma unroll
            for (int nt = 0; nt < 8; nt++) {
                const int bi = (nt >> 1) * 4 + (nt & 1) * 2;
                asm volatile(
                    "mma.sync.aligned.m16n8k16.row.col.f32.f16.f16.f32 "
                    "{%0,%1,%2,%3}, {%4,%5,%6,%7}, {%8,%9}, {%0,%1,%2,%3};"
                    : "+f"(d[mt][nt][0]), "+f"(d[mt][nt][1]),
                      "+f"(d[mt][nt][2]), "+f"(d[mt][nt][3])
                    : "r"(a[mt][0]), "r"(a[mt][1]), "r"(a[mt][2]), "r"(a[mt][3]),
                      "r"(b[bi]), "r"(b[bi+1]));
            }
        }
    }

    #pragma unroll
    for (int mt = 0; mt < 2; mt++) {
        const int r0 = m0 + mt*16 + (lane >> 2);
        const int iAr = i0 + r0, iBr = i0 + r0 + 8;
        #pragma unroll
        for (int nt = 0; nt < 8; nt++) {
            const int c = n0 + nt * 8 + (lane & 3) * 2;
            if (c < 128) {
                const float2 bb = *(const float2*)(b3 + c);
                __half2 h0 = __floats2half2_rn(d[mt][nt][0] + bb.x,
                                               d[mt][nt][1] + bb.y);
                __half2 h1 = __floats2half2_rn(d[mt][nt][2] + bb.x,
                                               d[mt][nt][3] + bb.y);
                *(uint32_t*)(g_Ah + (size_t)iAr * 128 + c) = *(uint32_t*)&h0;
                *(uint32_t*)(g_Ah + (size_t)iBr * 128 + c) = *(uint32_t*)&h1;
            } else {
                __half2 h0 = __floats2half2_rn(d[mt][nt][0], d[mt][nt][1]);
                __half2 h1 = __floats2half2_rn(d[mt][nt][2], d[mt][nt][3]);
                *(uint32_t*)(g_Bh + (size_t)iAr * 128 + (c - 128)) = *(uint32_t*)&h0;
                *(uint32_t*)(g_Bh + (size_t)iBr * 128 + (c - 128)) = *(uint32_t*)&h1;
            }
        }
    }
}

// ---------------- Kernel 4: EdgeConv2 fp16 mma, M=128/CTA, 512 thr ----------
#define A_ELEMS (128 * PADK)
#define B_ELEMS (256 * PADK)
#define CONV2_SMEM ((A_ELEMS + B_ELEMS) * 2)

__global__ __launch_bounds__(512, 1) void conv2m_kernel(
    const float* __restrict__ b4, float* __restrict__ out)
{
    extern __shared__ __align__(16) char smem[];
    __half* sA = (__half*)smem;
    __half* sB = sA + A_ELEMS;

    const int t    = threadIdx.x;
    const int lane = t & 31;
    const int w    = t >> 5;
    const int p0   = blockIdx.x * 16;

    {
        const int row = t >> 1, part = (t & 1) * 8;
        const uint4* s4 = (const uint4*)(g_w4h + (size_t)row * 128);
        uint4* d4 = (uint4*)(sB + row * PADK);
        #pragma unroll
        for (int g = 0; g < 8; g++) d4[part + g] = s4[part + g];
    }
    {
        const int r = t >> 2, q = t & 3;
        const int i = p0 + (r >> 3);
        const int j = g_knn[i * KNN + (r & 7)];
        const uint4* pa = (const uint4*)(g_Ah + (size_t)i * 128);
        const uint4* pb = (const uint4*)(g_Bh + (size_t)j * 128);
        uint4* dst = (uint4*)(sA + r * PADK);
        const __half2 z2 = __half2half2(__ushort_as_half(0));
        #pragma unroll
        for (int g = 0; g < 4; g++) {
            uint4 av = pa[q*4 + g];
            uint4 bv = pb[q*4 + g];
            uint4 o;
            __half2 s;
            s = __hmax2(__hadd2(*(__half2*)&av.x, *(__half2*)&bv.x), z2); o.x = *(uint32_t*)&s;
            s = __hmax2(__hadd2(*(__half2*)&av.y, *(__half2*)&bv.y), z2); o.y = *(uint32_t*)&s;
            s = __hmax2(__hadd2(*(__half2*)&av.z, *(__half2*)&bv.z), z2); o.z = *(uint32_t*)&s;
            s = __hmax2(__hadd2(*(__half2*)&av.w, *(__half2*)&bv.w), z2); o.w = *(uint32_t*)&s;
            dst[q*4 + g] = o;
        }
    }
    __syncthreads();

    const int mw  = w & 3;
    const int nwp = w >> 2;
    const int m0  = mw * 32;
    const int n0  = nwp * 64;

    const uint32_t sA32 = smem_u32(sA), sB32 = smem_u32(sB);
    const uint32_t aoff = ((uint32_t)(m0 + (lane & 15)) * PADK +
                           ((lane >> 4) & 1) * 8) * 2;
    const uint32_t boff = ((uint32_t)(n0 + ((lane >> 4) & 1) * 8 + (lane & 7)) * PADK +
                           ((lane >> 3) & 1) * 8) * 2;

    float d[2][8][4];
    #pragma unroll
    for (int mt = 0; mt < 2; mt++)
        #pragma unroll
        for (int nt = 0; nt < 8; nt++)
            { d[mt][nt][0]=0.f; d[mt][nt][1]=0.f; d[mt][nt][2]=0.f; d[mt][nt][3]=0.f; }

    #pragma unroll
    for (int k16 = 0; k16 < 8; k16++) {
        const uint32_t kb = k16 * 32;
        uint32_t a[2][4];
        #pragma unroll
        for (int mt = 0; mt < 2; mt++) {
            asm volatile(
                "ldmatrix.sync.aligned.m8n8.x4.shared.b16 {%0,%1,%2,%3}, [%4];"
                : "=r"(a[mt][0]), "=r"(a[mt][1]), "=r"(a[mt][2]), "=r"(a[mt][3])
                : "r"(sA32 + aoff + (uint32_t)mt * (16 * PADK * 2) + kb));
        }
        uint32_t b[16];
        #pragma unroll
        for (int ntp = 0; ntp < 4; ntp++) {
            asm volatile(
                "ldmatrix.sync.aligned.m8n8.x4.shared.b16 {%0,%1,%2,%3}, [%4];"
                : "=r"(b[ntp*4]), "=r"(b[ntp*4+1]), "=r"(b[ntp*4+2]), "=r"(b[ntp*4+3])
                : "r"(sB32 + boff + (uint32_t)ntp * (16 * PADK * 2) + kb));
        }
        #pragma unroll
        for (int mt = 0; mt < 2; mt++) {
            #pragma unroll
            for (int nt = 0; nt < 8; nt++) {
                const int bi = (nt >> 1) * 4 + (nt & 1) * 2;
                asm volatile(
                    "mma.sync.aligned.m16n8k16.row.col.f32.f16.f16.f32 "
                    "{%0,%1,%2,%3}, {%4,%5,%6,%7}, {%8,%9}, {%0,%1,%2,%3};"
                    : "+f"(d[mt][nt][0]), "+f"(d[mt][nt][1]),
                      "+f"(d[mt][nt][2]), "+f"(d[mt][nt][3])
                    : "r"(a[mt][0]), "r"(a[mt][1]), "r"(a[mt][2]), "r"(a[mt][3]),
                      "r"(b[bi]), "r"(b[bi+1]));
            }
        }
    }

    #pragma unroll
    for (int mt = 0; mt < 2; mt++) {
        #pragma unroll
        for (int nt = 0; nt < 8; nt++) {
            float v0 = d[mt][nt][0], v1 = d[mt][nt][1];
            float v2 = d[mt][nt][2], v3 = d[mt][nt][3];
            #pragma unroll
            for (int off = 4; off <= 16; off <<= 1) {
                v0 = fmaxf(v0, __shfl_xor_sync(0xFFFFFFFFu, v0, off));
                v1 = fmaxf(v1, __shfl_xor_sync(0xFFFFFFFFu, v1, off));
                v2 = fmaxf(v2, __shfl_xor_sync(0xFFFFFFFFu, v2, off));
                v3 = fmaxf(v3, __shfl_xor_sync(0xFFFFFFFFu, v3, off));
            }
            if (lane < 4) {
                const int c = n0 + nt * 8 + lane * 2;
                const float2 bb = *(const float2*)(b4 + c);
                const int pbase = p0 + mw * 4 + mt * 2;
                float2 o0; o0.x = v0 + bb.x; o0.y = v1 + bb.y;
                float2 o1; o1.x = v2 + bb.x; o1.y = v3 + bb.y;
                *(float2*)(out + (size_t)(pbase    ) * 256 + c) = o0;
                *(float2*)(out + (size_t)(pbase + 1) * 256 + c) = o1;
            }
        }
    }
}

// ---------------- launch -----------------------------------------------------
extern "C" void kernel_launch(void* const* d_in, const int* in_sizes, int n_in,
                              void* d_out, int out_size) {
    const float* pts = (const float*)d_in[0];
    const float* W1  = (const float*)d_in[1];
    const float* b1  = (const float*)d_in[2];
    const float* W2  = (const float*)d_in[3];
    const float* b2  = (const float*)d_in[4];
    const float* W3  = (const float*)d_in[5];
    const float* b3  = (const float*)d_in[6];
    const float* W4  = (const float*)d_in[7];
    const float* b4  = (const float*)d_in[8];
    float* out = (float*)d_out;

    cudaFuncSetAttribute(pre2t_kernel,
                         cudaFuncAttributeMaxDynamicSharedMemorySize, PRE2_SMEM);
    cudaFuncSetAttribute(conv2m_kernel,
                         cudaFuncAttributeMaxDynamicSharedMemorySize, CONV2_SMEM);

    w2conv_kernel<<<32, 256>>>(W2);
    w3conv_kernel<<<64, 256>>>(W3);
    w4conv_kernel<<<128, 256>>>(W4);
    knn_kernel   <<<NPTS/16, 256>>>(pts);    // 4th launch -> profiled
    conv1_kernel <<<NPTS/16, 256>>>(pts, W1, b1, b2);
    pre2t_kernel <<<NPTS/64, 256, PRE2_SMEM>>>(b3);
    conv2m_kernel<<<NPTS/16, 512, CONV2_SMEM>>>(b4, out);
}